// round 2
// baseline (speedup 1.0000x reference)
#include <cuda_runtime.h>

#define EPS 1e-5f

// ---------------- device scratch (no allocations allowed) ----------------
__device__ float g_Hmk[1024 * 512];    // [b][c:8][l:64]
__device__ float g_Hml[1024 * 256];    // [b][c:8][k:32]
__device__ float g_A0[1024 * 4096];    // layer0 AP post-relu pre-BN [b][o:64][l:64]
__device__ float g_U0[1024 * 2048];    // layer0 UE [b][o:64][k:32]
__device__ float g_A1[1024 * 4096];
__device__ float g_U1[1024 * 2048];
__device__ float g_stats[512];         // L0: apS,apSS,ueS,ueSS @0,64,128,192; L1 @256..
__device__ float g_TQa[4096];          // 2*Qh1[0]^T [c][o]
__device__ float g_TQu[4096];          // 2*Qh1[2]^T
__device__ float g_TPa[512];           // 0.1*Ph1[0]^T [c:8][o:64]
__device__ float g_TPu[512];

static __device__ __forceinline__ float4 ld4(const float* p) { return *reinterpret_cast<const float4*>(p); }
static __device__ __forceinline__ float2 ld2(const float* p) { return *reinterpret_cast<const float2*>(p); }
static __device__ __forceinline__ void st4(float* p, float4 v) { *reinterpret_cast<float4*>(p) = v; }

// ---------------- K0: zero stats + transpose/pre-scale layer1 weights ----------------
__global__ void __launch_bounds__(256) k0_prep(const float* __restrict__ Qh,
                                               const float* __restrict__ Ph) {
    int t = threadIdx.x;
    for (int i = t; i < 512; i += 256) g_stats[i] = 0.f;
    for (int i = t; i < 4096; i += 256) {
        int c = i >> 6, o = i & 63;
        g_TQa[i] = 2.f * Qh[4 * 4096 + o * 64 + c];   // Qs_hidden[1][0]
        g_TQu[i] = 2.f * Qh[6 * 4096 + o * 64 + c];   // Qs_hidden[1][2]
    }
    for (int i = t; i < 512; i += 256) {
        int c = i >> 6, o = i & 63;
        g_TPa[i] = 0.1f * Ph[1024 + o * 8 + c];       // Ps_hidden[1][0]
        g_TPu[i] = 0.1f * Ph[1536 + o * 8 + c];       // Ps_hidden[1][1]
    }
}

// ---------------- K1: H reductions + fused layer0 + stats ----------------
__global__ void __launch_bounds__(256) k1_l0(const float* __restrict__ Hr,
                                             const float* __restrict__ Hi,
                                             const float* __restrict__ Ph) {
    int b = blockIdx.x, t = threadIdx.x, w = t >> 5, lane = t & 31;
    __shared__ float sHmk[512];          // [c:8][l:64]
    __shared__ float sHml[256];          // [c:8][k:32]
    __shared__ float4 sLr[8][32];
    __shared__ float4 sLi[8][32];
    __shared__ float sOA[64 * 65];       // padded [o][l]
    __shared__ float sOU[64 * 33];       // padded [o][k]

    const float4* hr4 = reinterpret_cast<const float4*>(Hr) + (size_t)b * 2048;
    const float4* hi4 = reinterpret_cast<const float4*>(Hi) + (size_t)b * 2048;
    float4 ar = make_float4(0, 0, 0, 0), ai = make_float4(0, 0, 0, 0);
#pragma unroll
    for (int i = 0; i < 8; i++) {
        int l = i * 8 + w;
        float4 r = hr4[l * 32 + lane];
        float4 m = hi4[l * 32 + lane];
        ar.x += r.x; ar.y += r.y; ar.z += r.z; ar.w += r.w;
        ai.x += m.x; ai.y += m.y; ai.z += m.z; ai.w += m.w;
#pragma unroll
        for (int o = 16; o; o >>= 1) {
            r.x += __shfl_xor_sync(0xffffffffu, r.x, o);
            r.y += __shfl_xor_sync(0xffffffffu, r.y, o);
            r.z += __shfl_xor_sync(0xffffffffu, r.z, o);
            r.w += __shfl_xor_sync(0xffffffffu, r.w, o);
            m.x += __shfl_xor_sync(0xffffffffu, m.x, o);
            m.y += __shfl_xor_sync(0xffffffffu, m.y, o);
            m.z += __shfl_xor_sync(0xffffffffu, m.z, o);
            m.w += __shfl_xor_sync(0xffffffffu, m.w, o);
        }
        if (lane == 0) {
            const float inv = 1.f / 32.f;
            sHmk[0 * 64 + l] = r.x * inv; sHmk[1 * 64 + l] = r.y * inv;
            sHmk[2 * 64 + l] = r.z * inv; sHmk[3 * 64 + l] = r.w * inv;
            sHmk[4 * 64 + l] = m.x * inv; sHmk[5 * 64 + l] = m.y * inv;
            sHmk[6 * 64 + l] = m.z * inv; sHmk[7 * 64 + l] = m.w * inv;
        }
    }
    sLr[w][lane] = ar; sLi[w][lane] = ai;
    __syncthreads();
    if (t < 32) {
        float4 s = make_float4(0, 0, 0, 0), si = make_float4(0, 0, 0, 0);
#pragma unroll
        for (int w2 = 0; w2 < 8; w2++) {
            float4 a = sLr[w2][t], c = sLi[w2][t];
            s.x += a.x; s.y += a.y; s.z += a.z; s.w += a.w;
            si.x += c.x; si.y += c.y; si.z += c.z; si.w += c.w;
        }
        const float inv = 1.f / 64.f;
        sHml[0 * 32 + t] = s.x * inv;  sHml[1 * 32 + t] = s.y * inv;
        sHml[2 * 32 + t] = s.z * inv;  sHml[3 * 32 + t] = s.w * inv;
        sHml[4 * 32 + t] = si.x * inv; sHml[5 * 32 + t] = si.y * inv;
        sHml[6 * 32 + t] = si.z * inv; sHml[7 * 32 + t] = si.w * inv;
    }
    __syncthreads();
    for (int i = t; i < 512; i += 256) g_Hmk[(size_t)b * 512 + i] = sHmk[i];
    g_Hml[(size_t)b * 256 + t] = sHml[t];

    // layer0: A inputs are zero => only 0.1*P@Hmean terms, then relu + stats
    int o = t >> 2, q = t & 3;
    float pa[8], pu[8];
#pragma unroll
    for (int c = 0; c < 8; c++) {
        pa[c] = 0.1f * Ph[o * 8 + c];          // Ps_hidden[0][0]
        pu[c] = 0.1f * Ph[512 + o * 8 + c];    // Ps_hidden[0][1]
    }
    float ps = 0.f, pss = 0.f;
#pragma unroll
    for (int j = 0; j < 16; j++) {
        int l = q * 16 + j;
        float v = 0.f;
#pragma unroll
        for (int c = 0; c < 8; c++) v += pa[c] * sHmk[c * 64 + l];
        v = fmaxf(v, 0.f);
        sOA[o * 65 + l] = v; ps += v; pss += v * v;
    }
    ps += __shfl_xor_sync(0xffffffffu, ps, 1);  ps += __shfl_xor_sync(0xffffffffu, ps, 2);
    pss += __shfl_xor_sync(0xffffffffu, pss, 1); pss += __shfl_xor_sync(0xffffffffu, pss, 2);
    if (q == 0) { atomicAdd(&g_stats[o], ps); atomicAdd(&g_stats[64 + o], pss); }

    float us = 0.f, uss = 0.f;
#pragma unroll
    for (int j = 0; j < 8; j++) {
        int k = q * 8 + j;
        float v = 0.f;
#pragma unroll
        for (int c = 0; c < 8; c++) v += pu[c] * sHml[c * 32 + k];
        v = fmaxf(v, 0.f);
        sOU[o * 33 + k] = v; us += v; uss += v * v;
    }
    us += __shfl_xor_sync(0xffffffffu, us, 1);  us += __shfl_xor_sync(0xffffffffu, us, 2);
    uss += __shfl_xor_sync(0xffffffffu, uss, 1); uss += __shfl_xor_sync(0xffffffffu, uss, 2);
    if (q == 0) { atomicAdd(&g_stats[128 + o], us); atomicAdd(&g_stats[192 + o], uss); }
    __syncthreads();

    for (int i = t; i < 4096; i += 256) {
        int oo = i >> 6, l = i & 63;
        g_A0[(size_t)b * 4096 + i] = sOA[oo * 65 + l];
    }
    for (int i = t; i < 2048; i += 256) {
        int oo = i >> 5, k = i & 31;
        g_U0[(size_t)b * 2048 + i] = sOU[oo * 33 + k];
    }
}

// ---------------- K2: layer1 (lazy BN on layer0, GEMMs, relu, stats) ----------------
struct __align__(16) SK2 {
    float AP[4096], UE[2048], Qa[4096], Qu[4096];
    float Pa[512], Pu[512], Hmk[512], Hml[256];
    float ScA[64], ShA[64], ScU[64], ShU[64];
    float MA[64], MU[64], BA[64], BU[64];
};

__global__ void __launch_bounds__(256) k2_l1(const float* __restrict__ Qh,
                                             const float* __restrict__ gamma,
                                             const float* __restrict__ beta) {
    extern __shared__ __align__(16) char sraw[];
    SK2& S = *reinterpret_cast<SK2*>(sraw);
    int b = blockIdx.x, t = threadIdx.x;

    if (t < 64) {
        float m = g_stats[t] * (1.f / 65536.f);
        float v = g_stats[64 + t] * (1.f / 65536.f) - m * m;
        float sc = gamma[t] * rsqrtf(v + EPS);
        S.ScA[t] = sc; S.ShA[t] = beta[t] - m * sc;
        float mu = g_stats[128 + t] * (1.f / 32768.f);
        float vu = g_stats[192 + t] * (1.f / 32768.f) - mu * mu;
        float su = gamma[t] * rsqrtf(vu + EPS);
        S.ScU[t] = su; S.ShU[t] = beta[t] - mu * su;
    }
    for (int i = t; i < 4096; i += 256) { S.Qa[i] = g_TQa[i]; S.Qu[i] = g_TQu[i]; }
    for (int i = t; i < 512; i += 256) {
        S.Pa[i] = g_TPa[i]; S.Pu[i] = g_TPu[i]; S.Hmk[i] = g_Hmk[(size_t)b * 512 + i];
    }
    S.Hml[t] = g_Hml[(size_t)b * 256 + t];
    __syncthreads();
    for (int i = t; i < 4096; i += 256) {
        int c = i >> 6;
        S.AP[i] = g_A0[(size_t)b * 4096 + i] * S.ScA[c] + S.ShA[c];
    }
    for (int i = t; i < 2048; i += 256) {
        int c = i >> 5;
        S.UE[i] = g_U0[(size_t)b * 2048 + i] * S.ScU[c] + S.ShU[c];
    }
    __syncthreads();
    if (t < 64) {
        float s = 0.f;
        for (int j = 0; j < 32; j++) s += S.UE[t * 32 + ((t + j) & 31)];
        S.MU[t] = s * (1.f / 32.f);
        float s2 = 0.f;
        for (int j = 0; j < 64; j++) s2 += S.AP[t * 64 + ((t + j) & 63)];
        S.MA[t] = s2 * (1.f / 64.f);
    }
    __syncthreads();
    if (t < 64) {
        const float* q2a = Qh + 5 * 4096 + t * 64;   // Qs_hidden[1][1]
        const float* q2u = Qh + 7 * 4096 + t * 64;   // Qs_hidden[1][3]
        float s = 0.f, su = 0.f;
        for (int c = 0; c < 64; c++) { s += q2a[c] * S.MU[c]; su += q2u[c] * S.MA[c]; }
        S.BA[t] = 2.f * s; S.BU[t] = 2.f * su;
    }
    __syncthreads();

    // AP GEMM: thread tile 4(o) x 4(l);  o0 = (t>>4)*4, l0 = (t&15)*4
    int o0 = (t >> 4) * 4, l0 = (t & 15) * 4;
    float acc[4][4];
#pragma unroll
    for (int i = 0; i < 4; i++) {
        float bi = S.BA[o0 + i];
#pragma unroll
        for (int j = 0; j < 4; j++) acc[i][j] = bi;
    }
#pragma unroll
    for (int c = 0; c < 8; c++) {
        float4 p = ld4(&S.Pa[c * 64 + o0]);
        float4 h = ld4(&S.Hmk[c * 64 + l0]);
        acc[0][0] += p.x * h.x; acc[0][1] += p.x * h.y; acc[0][2] += p.x * h.z; acc[0][3] += p.x * h.w;
        acc[1][0] += p.y * h.x; acc[1][1] += p.y * h.y; acc[1][2] += p.y * h.z; acc[1][3] += p.y * h.w;
        acc[2][0] += p.z * h.x; acc[2][1] += p.z * h.y; acc[2][2] += p.z * h.z; acc[2][3] += p.z * h.w;
        acc[3][0] += p.w * h.x; acc[3][1] += p.w * h.y; acc[3][2] += p.w * h.z; acc[3][3] += p.w * h.w;
    }
#pragma unroll
    for (int c = 0; c < 64; c++) {
        float4 qv = ld4(&S.Qa[c * 64 + o0]);
        float4 av = ld4(&S.AP[c * 64 + l0]);
        acc[0][0] += qv.x * av.x; acc[0][1] += qv.x * av.y; acc[0][2] += qv.x * av.z; acc[0][3] += qv.x * av.w;
        acc[1][0] += qv.y * av.x; acc[1][1] += qv.y * av.y; acc[1][2] += qv.y * av.z; acc[1][3] += qv.y * av.w;
        acc[2][0] += qv.z * av.x; acc[2][1] += qv.z * av.y; acc[2][2] += qv.z * av.z; acc[2][3] += qv.z * av.w;
        acc[3][0] += qv.w * av.x; acc[3][1] += qv.w * av.y; acc[3][2] += qv.w * av.z; acc[3][3] += qv.w * av.w;
    }

    // UE GEMM: thread tile 2(o) x 4(k);  ou = (t>>3)*2, kq = (t&7)*4
    int ou = (t >> 3) * 2, kq = (t & 7) * 4;
    float au[2][4];
#pragma unroll
    for (int i = 0; i < 2; i++) {
        float bi = S.BU[ou + i];
#pragma unroll
        for (int j = 0; j < 4; j++) au[i][j] = bi;
    }
#pragma unroll
    for (int c = 0; c < 8; c++) {
        float2 p = ld2(&S.Pu[c * 64 + ou]);
        float4 h = ld4(&S.Hml[c * 32 + kq]);
        au[0][0] += p.x * h.x; au[0][1] += p.x * h.y; au[0][2] += p.x * h.z; au[0][3] += p.x * h.w;
        au[1][0] += p.y * h.x; au[1][1] += p.y * h.y; au[1][2] += p.y * h.z; au[1][3] += p.y * h.w;
    }
#pragma unroll
    for (int c = 0; c < 64; c++) {
        float2 qv = ld2(&S.Qu[c * 64 + ou]);
        float4 uv = ld4(&S.UE[c * 32 + kq]);
        au[0][0] += qv.x * uv.x; au[0][1] += qv.x * uv.y; au[0][2] += qv.x * uv.z; au[0][3] += qv.x * uv.w;
        au[1][0] += qv.y * uv.x; au[1][1] += qv.y * uv.y; au[1][2] += qv.y * uv.z; au[1][3] += qv.y * uv.w;
    }
    __syncthreads();   // all GEMM reads done; reuse AP/UE as output staging

#pragma unroll
    for (int i = 0; i < 4; i++)
        st4(&S.AP[(o0 + i) * 64 + l0],
            make_float4(fmaxf(acc[i][0], 0.f), fmaxf(acc[i][1], 0.f),
                        fmaxf(acc[i][2], 0.f), fmaxf(acc[i][3], 0.f)));
#pragma unroll
    for (int i = 0; i < 2; i++)
        st4(&S.UE[(ou + i) * 32 + kq],
            make_float4(fmaxf(au[i][0], 0.f), fmaxf(au[i][1], 0.f),
                        fmaxf(au[i][2], 0.f), fmaxf(au[i][3], 0.f)));
    __syncthreads();

    if (t < 64) {
        float s = 0.f, ss = 0.f;
        for (int j = 0; j < 64; j++) { float x = S.AP[t * 64 + ((t + j) & 63)]; s += x; ss += x * x; }
        atomicAdd(&g_stats[256 + t], s); atomicAdd(&g_stats[320 + t], ss);
        float su = 0.f, ssu = 0.f;
        for (int j = 0; j < 32; j++) { float x = S.UE[t * 32 + ((t + j) & 31)]; su += x; ssu += x * x; }
        atomicAdd(&g_stats[384 + t], su); atomicAdd(&g_stats[448 + t], ssu);
    }
    float4* dA = reinterpret_cast<float4*>(g_A1 + (size_t)b * 4096);
    const float4* sA4 = reinterpret_cast<const float4*>(S.AP);
    for (int i = t; i < 1024; i += 256) dA[i] = sA4[i];
    float4* dU = reinterpret_cast<float4*>(g_U1 + (size_t)b * 2048);
    const float4* sU4 = reinterpret_cast<const float4*>(S.UE);
    for (int i = t; i < 512; i += 256) dU[i] = sU4[i];
}

// ---------------- K3: output layer + per-k norm + fused Vhat*Phat ----------------
__global__ void __launch_bounds__(256) k3_out(const float* __restrict__ Vh,
                                              const float* __restrict__ Qo,
                                              const float* __restrict__ Po,
                                              const float* __restrict__ gamma,
                                              const float* __restrict__ beta,
                                              float* __restrict__ out) {
    __shared__ float sAP[4096];          // normalized layer1 AP [c][l]
    __shared__ float sQ[2048];           // 2*Qo0^T [c][k]
    __shared__ float sPo[256];           // 0.1*Po0^T [c8][k]
    __shared__ float sHmk[512];
    __shared__ float sV[32 * 65];        // V[k][l], padded
    __shared__ float sMU[64], sB[32], sFac[32], sScA[64], sShA[64];
    int b = blockIdx.x, t = threadIdx.x;

    if (t < 64) {
        float m = g_stats[256 + t] * (1.f / 65536.f);
        float v = g_stats[320 + t] * (1.f / 65536.f) - m * m;
        float sc = gamma[64 + t] * rsqrtf(v + EPS);
        sScA[t] = sc; sShA[t] = beta[64 + t] - m * sc;
        float mu = g_stats[384 + t] * (1.f / 32768.f);
        float vu = g_stats[448 + t] * (1.f / 32768.f) - mu * mu;
        float su = gamma[64 + t] * rsqrtf(vu + EPS);
        float sh = beta[64 + t] - mu * su;
        const float* ue = g_U1 + (size_t)b * 2048 + t * 32;
        float s = 0.f;
        for (int k = 0; k < 32; k++) s += ue[k];
        sMU[t] = (s * (1.f / 32.f)) * su + sh;        // mean of BN'd UE1
    }
    for (int i = t; i < 2048; i += 256) {
        int c = i >> 5, k = i & 31;
        sQ[i] = 2.f * Qo[k * 64 + c];                 // Qs_out[0]
    }
    { int c = t >> 5, k = t & 31; sPo[t] = 0.1f * Po[k * 8 + c]; }  // Ps_out[0]
    for (int i = t; i < 512; i += 256) sHmk[i] = g_Hmk[(size_t)b * 512 + i];
    __syncthreads();
    for (int i = t; i < 4096; i += 256) {
        int c = i >> 6;
        sAP[i] = g_A1[(size_t)b * 4096 + i] * sScA[c] + sShA[c];
    }
    __syncthreads();
    if (t < 32) {
        const float* q2 = Qo + 2048 + t * 64;         // Qs_out[1]
        float s = 0.f;
        for (int c = 0; c < 64; c++) s += q2[c] * sMU[c];
        sB[t] = 2.f * s;
    }
    __syncthreads();

    // GEMM 32(k) x 64(l) x 72: thread tile 4(k) x 2(l)
    int ko = (t >> 5) * 4, lo = (t & 31) * 2;
    float acc[4][2];
#pragma unroll
    for (int i = 0; i < 4; i++) { acc[i][0] = sB[ko + i]; acc[i][1] = sB[ko + i]; }
#pragma unroll
    for (int c = 0; c < 8; c++) {
        float4 p = ld4(&sPo[c * 32 + ko]);
        float h0 = sHmk[c * 64 + lo], h1 = sHmk[c * 64 + lo + 1];
        acc[0][0] += p.x * h0; acc[0][1] += p.x * h1;
        acc[1][0] += p.y * h0; acc[1][1] += p.y * h1;
        acc[2][0] += p.z * h0; acc[2][1] += p.z * h1;
        acc[3][0] += p.w * h0; acc[3][1] += p.w * h1;
    }
#pragma unroll
    for (int c = 0; c < 64; c++) {
        float4 qv = ld4(&sQ[c * 32 + ko]);
        float2 a = ld2(&sAP[c * 64 + lo]);
        acc[0][0] += qv.x * a.x; acc[0][1] += qv.x * a.y;
        acc[1][0] += qv.y * a.x; acc[1][1] += qv.y * a.y;
        acc[2][0] += qv.z * a.x; acc[2][1] += qv.z * a.y;
        acc[3][0] += qv.w * a.x; acc[3][1] += qv.w * a.y;
    }
#pragma unroll
    for (int i = 0; i < 4; i++) {
        sV[(ko + i) * 65 + lo] = acc[i][0];
        sV[(ko + i) * 65 + lo + 1] = acc[i][1];
    }
    __syncthreads();
    if (t < 32) {
        float ss = 0.f;
        for (int j = 0; j < 64; j++) { float x = sV[t * 65 + ((t + j) & 63)]; ss += x * x; }
        sFac[t] = 8.f * rsqrtf(ss);                   // sqrt(L)=8
    }
    __syncthreads();

    const float4* v4 = reinterpret_cast<const float4*>(Vh) + (size_t)b * 2048;
    float4* o4 = reinterpret_cast<float4*>(out) + (size_t)b * 2048;
    for (int i = t; i < 2048; i += 256) {
        int l = i >> 5, k = i & 31;
        float pf = sV[k * 65 + l] * sFac[k];
        float4 v = v4[i];
        v.x *= pf; v.y *= pf; v.z *= pf; v.w *= pf;
        o4[i] = v;
    }
}

// ---------------- host ----------------
extern "C" void kernel_launch(void* const* d_in, const int* in_sizes, int n_in,
                              void* d_out, int out_size) {
    (void)in_sizes; (void)n_in; (void)out_size;
    const float* Hr = (const float*)d_in[0];
    const float* Hi = (const float*)d_in[1];
    const float* Vh = (const float*)d_in[2];
    const float* Qh = (const float*)d_in[3];
    const float* Ph = (const float*)d_in[4];
    const float* Qo = (const float*)d_in[5];
    const float* Po = (const float*)d_in[6];
    const float* gamma = (const float*)d_in[7];
    const float* beta = (const float*)d_in[8];

    cudaFuncSetAttribute(k2_l1, cudaFuncAttributeMaxDynamicSharedMemorySize, (int)sizeof(SK2));

    k0_prep<<<1, 256>>>(Qh, Ph);
    k1_l0<<<1024, 256>>>(Hr, Hi, Ph);
    k2_l1<<<1024, 256, sizeof(SK2)>>>(Qh, gamma, beta);
    k3_out<<<1024, 256>>>(Vh, Qo, Po, gamma, beta, (float*)d_out);
}

// round 3
// speedup vs baseline: 1.1525x; 1.1525x over previous
#include <cuda_runtime.h>

#define EPS 1e-5f

// ---------------- device scratch ----------------
__device__ float g_Hmk[1024 * 512];    // [b][c:8][l:64]
__device__ float g_Hml[1024 * 256];    // [b][c:8][k:32]
__device__ float g_A1[1024 * 4096];    // layer1 AP post-relu raw [b][o:64][l:64]
__device__ float g_U1m[1024 * 64];     // mean over k of layer1 UE post-relu raw [b][c:64]
__device__ float g_Phat[1024 * 2048];  // [b][l:64][k:32]
__device__ float g_stats[512];         // L0: apS,apSS,ueS,ueSS @0,64,128,192; L1 @256..
__device__ float g_TQa[4096];          // 2*Qh1[0]^T [c][o]
__device__ float g_TQu[4096];          // 2*Qh1[2]^T
__device__ float g_TPa[512];           // 0.1*Ph1[0]^T [c:8][o:64]
__device__ float g_TPu[512];
__device__ float g_TQo[2048];          // 2*Qo[0]^T [c:64][k:32]
__device__ float g_TPo[256];           // 0.1*Po[0]^T [c:8][k:32]

static __device__ __forceinline__ float4 ld4(const float* p) { return *reinterpret_cast<const float4*>(p); }
static __device__ __forceinline__ float2 ld2(const float* p) { return *reinterpret_cast<const float2*>(p); }
static __device__ __forceinline__ void st4(float* p, float4 v) { *reinterpret_cast<float4*>(p) = v; }

// ---------------- K0: zero stats + transpose/pre-scale weights ----------------
__global__ void __launch_bounds__(256) k0_prep(const float* __restrict__ Qh,
                                               const float* __restrict__ Ph,
                                               const float* __restrict__ Qo,
                                               const float* __restrict__ Po) {
    int t = threadIdx.x;
    for (int i = t; i < 512; i += 256) g_stats[i] = 0.f;
    for (int i = t; i < 4096; i += 256) {
        int c = i >> 6, o = i & 63;
        g_TQa[i] = 2.f * Qh[4 * 4096 + o * 64 + c];   // Qs_hidden[1][0]
        g_TQu[i] = 2.f * Qh[6 * 4096 + o * 64 + c];   // Qs_hidden[1][2]
    }
    for (int i = t; i < 512; i += 256) {
        int c = i >> 6, o = i & 63;
        g_TPa[i] = 0.1f * Ph[1024 + o * 8 + c];       // Ps_hidden[1][0]
        g_TPu[i] = 0.1f * Ph[1536 + o * 8 + c];       // Ps_hidden[1][1]
    }
    for (int i = t; i < 2048; i += 256) {
        int c = i >> 5, k = i & 31;
        g_TQo[i] = 2.f * Qo[k * 64 + c];              // Qs_out[0]
    }
    { int c = t >> 5, k = t & 31; g_TPo[t] = 0.1f * Po[k * 8 + c]; }  // Ps_out[0]
}

// ---------------- K1: single pass over H -> Hmk/Hml + layer0 stats ----------------
struct SK1 {
    float S[8][64 * 33];    // [c][l*33+k] staged H values (conflict-free)
    float Hmk[512];         // [c:8][l:64]
    float Hml[256];         // [c:8][k:32]
};

__global__ void __launch_bounds__(256) k1_l0(const float* __restrict__ Hr,
                                             const float* __restrict__ Hi,
                                             const float* __restrict__ Ph) {
    extern __shared__ __align__(16) char sraw1[];
    SK1& S = *reinterpret_cast<SK1*>(sraw1);
    int b = blockIdx.x, t = threadIdx.x, w = t >> 5, lane = t & 31;

    const float4* hr4 = reinterpret_cast<const float4*>(Hr) + (size_t)b * 2048;
    const float4* hi4 = reinterpret_cast<const float4*>(Hi) + (size_t)b * 2048;
#pragma unroll
    for (int i = 0; i < 8; i++) {
        int l = i * 8 + w;
        float4 r = hr4[l * 32 + lane];
        float4 m = hi4[l * 32 + lane];
        int base = l * 33 + lane;
        S.S[0][base] = r.x; S.S[1][base] = r.y; S.S[2][base] = r.z; S.S[3][base] = r.w;
        S.S[4][base] = m.x; S.S[5][base] = m.y; S.S[6][base] = m.z; S.S[7][base] = m.w;
    }
    __syncthreads();

    // Hmk[c][l] = mean over k
#pragma unroll
    for (int p = 0; p < 2; p++) {
        int idx = t + p * 256;
        int c = idx >> 6, l = idx & 63;
        float s = 0.f;
#pragma unroll
        for (int k = 0; k < 32; k++) s += S.S[c][l * 33 + k];
        float v = s * (1.f / 32.f);
        S.Hmk[idx] = v;
        g_Hmk[(size_t)b * 512 + idx] = v;
    }
    // Hml[c][k] = mean over l
    {
        int c = t >> 5, k = t & 31;
        float s = 0.f;
#pragma unroll
        for (int l = 0; l < 64; l++) s += S.S[c][l * 33 + k];
        float v = s * (1.f / 64.f);
        S.Hml[t] = v;
        g_Hml[(size_t)b * 256 + t] = v;
    }
    __syncthreads();

    // layer0 stats only (A inputs zero => relu(0.1*P0 @ Hmean)); nothing stored
    int o = t >> 2, q = t & 3;
    float pa[8], pu[8];
#pragma unroll
    for (int c = 0; c < 8; c++) {
        pa[c] = 0.1f * Ph[o * 8 + c];          // Ps_hidden[0][0]
        pu[c] = 0.1f * Ph[512 + o * 8 + c];    // Ps_hidden[0][1]
    }
    float ps = 0.f, pss = 0.f;
#pragma unroll
    for (int j = 0; j < 16; j++) {
        int l = q * 16 + j;
        float v = 0.f;
#pragma unroll
        for (int c = 0; c < 8; c++) v += pa[c] * S.Hmk[c * 64 + l];
        v = fmaxf(v, 0.f);
        ps += v; pss += v * v;
    }
    ps += __shfl_xor_sync(0xffffffffu, ps, 1);  ps += __shfl_xor_sync(0xffffffffu, ps, 2);
    pss += __shfl_xor_sync(0xffffffffu, pss, 1); pss += __shfl_xor_sync(0xffffffffu, pss, 2);
    if (q == 0) { atomicAdd(&g_stats[o], ps); atomicAdd(&g_stats[64 + o], pss); }

    float us = 0.f, uss = 0.f;
#pragma unroll
    for (int j = 0; j < 8; j++) {
        int k = q * 8 + j;
        float v = 0.f;
#pragma unroll
        for (int c = 0; c < 8; c++) v += pu[c] * S.Hml[c * 32 + k];
        v = fmaxf(v, 0.f);
        us += v; uss += v * v;
    }
    us += __shfl_xor_sync(0xffffffffu, us, 1);  us += __shfl_xor_sync(0xffffffffu, us, 2);
    uss += __shfl_xor_sync(0xffffffffu, uss, 1); uss += __shfl_xor_sync(0xffffffffu, uss, 2);
    if (q == 0) { atomicAdd(&g_stats[128 + o], us); atomicAdd(&g_stats[192 + o], uss); }
}

// ---------------- K2: recompute layer0 (lazy BN), layer1 GEMMs, relu, stats ----------------
struct __align__(16) SK2 {
    float AP[4096], UE[2048], Qa[4096], Qu[4096];
    float Pa[512], Pu[512], P0a[512], P0u[512];
    float Hmk[512], Hml[256];
    float ScA[64], ShA[64], ScU[64], ShU[64];
    float MA[64], MU[64], BA[64], BU[64];
};

__global__ void __launch_bounds__(256) k2_l1(const float* __restrict__ Qh,
                                             const float* __restrict__ Ph,
                                             const float* __restrict__ gamma,
                                             const float* __restrict__ beta) {
    extern __shared__ __align__(16) char sraw[];
    SK2& S = *reinterpret_cast<SK2*>(sraw);
    int b = blockIdx.x, t = threadIdx.x;

    if (t < 64) {
        float m = g_stats[t] * (1.f / 65536.f);
        float v = g_stats[64 + t] * (1.f / 65536.f) - m * m;
        float sc = gamma[t] * rsqrtf(v + EPS);
        S.ScA[t] = sc; S.ShA[t] = beta[t] - m * sc;
        float mu = g_stats[128 + t] * (1.f / 32768.f);
        float vu = g_stats[192 + t] * (1.f / 32768.f) - mu * mu;
        float su = gamma[t] * rsqrtf(vu + EPS);
        S.ScU[t] = su; S.ShU[t] = beta[t] - mu * su;
    }
    for (int i = t; i < 4096; i += 256) { S.Qa[i] = g_TQa[i]; S.Qu[i] = g_TQu[i]; }
    for (int i = t; i < 512; i += 256) {
        S.Pa[i] = g_TPa[i]; S.Pu[i] = g_TPu[i];
        S.P0a[i] = 0.1f * Ph[i]; S.P0u[i] = 0.1f * Ph[512 + i];
        S.Hmk[i] = g_Hmk[(size_t)b * 512 + i];
    }
    S.Hml[t] = g_Hml[(size_t)b * 256 + t];
    __syncthreads();

    // recompute normalized layer0 outputs
    {
        int l = t & 63, og = t >> 6;
#pragma unroll
        for (int j = 0; j < 16; j++) {
            int o = og * 16 + j;
            float r = 0.f;
#pragma unroll
            for (int c = 0; c < 8; c++) r += S.P0a[o * 8 + c] * S.Hmk[c * 64 + l];
            S.AP[o * 64 + l] = fmaxf(r, 0.f) * S.ScA[o] + S.ShA[o];
        }
        int k = t & 31, og2 = t >> 5;
#pragma unroll
        for (int j = 0; j < 8; j++) {
            int o = og2 * 8 + j;
            float r = 0.f;
#pragma unroll
            for (int c = 0; c < 8; c++) r += S.P0u[o * 8 + c] * S.Hml[c * 32 + k];
            S.UE[o * 32 + k] = fmaxf(r, 0.f) * S.ScU[o] + S.ShU[o];
        }
    }
    __syncthreads();
    if (t < 64) {
        float s = 0.f;
        for (int j = 0; j < 32; j++) s += S.UE[t * 32 + ((t + j) & 31)];
        S.MU[t] = s * (1.f / 32.f);
        float s2 = 0.f;
        for (int j = 0; j < 64; j++) s2 += S.AP[t * 64 + ((t + j) & 63)];
        S.MA[t] = s2 * (1.f / 64.f);
    }
    __syncthreads();
    if (t < 64) {
        const float* q2a = Qh + 5 * 4096 + t * 64;   // Qs_hidden[1][1]
        const float* q2u = Qh + 7 * 4096 + t * 64;   // Qs_hidden[1][3]
        float s = 0.f, su = 0.f;
        for (int c = 0; c < 64; c++) { s += q2a[c] * S.MU[c]; su += q2u[c] * S.MA[c]; }
        S.BA[t] = 2.f * s; S.BU[t] = 2.f * su;
    }
    __syncthreads();

    // AP GEMM: 4(o) x 4(l) tile
    int o0 = (t >> 4) * 4, l0 = (t & 15) * 4;
    float acc[4][4];
#pragma unroll
    for (int i = 0; i < 4; i++) {
        float bi = S.BA[o0 + i];
#pragma unroll
        for (int j = 0; j < 4; j++) acc[i][j] = bi;
    }
#pragma unroll
    for (int c = 0; c < 8; c++) {
        float4 p = ld4(&S.Pa[c * 64 + o0]);
        float4 h = ld4(&S.Hmk[c * 64 + l0]);
        acc[0][0] += p.x * h.x; acc[0][1] += p.x * h.y; acc[0][2] += p.x * h.z; acc[0][3] += p.x * h.w;
        acc[1][0] += p.y * h.x; acc[1][1] += p.y * h.y; acc[1][2] += p.y * h.z; acc[1][3] += p.y * h.w;
        acc[2][0] += p.z * h.x; acc[2][1] += p.z * h.y; acc[2][2] += p.z * h.z; acc[2][3] += p.z * h.w;
        acc[3][0] += p.w * h.x; acc[3][1] += p.w * h.y; acc[3][2] += p.w * h.z; acc[3][3] += p.w * h.w;
    }
#pragma unroll
    for (int c = 0; c < 64; c++) {
        float4 qv = ld4(&S.Qa[c * 64 + o0]);
        float4 av = ld4(&S.AP[c * 64 + l0]);
        acc[0][0] += qv.x * av.x; acc[0][1] += qv.x * av.y; acc[0][2] += qv.x * av.z; acc[0][3] += qv.x * av.w;
        acc[1][0] += qv.y * av.x; acc[1][1] += qv.y * av.y; acc[1][2] += qv.y * av.z; acc[1][3] += qv.y * av.w;
        acc[2][0] += qv.z * av.x; acc[2][1] += qv.z * av.y; acc[2][2] += qv.z * av.z; acc[2][3] += qv.z * av.w;
        acc[3][0] += qv.w * av.x; acc[3][1] += qv.w * av.y; acc[3][2] += qv.w * av.z; acc[3][3] += qv.w * av.w;
    }

    // UE GEMM: 2(o) x 4(k) tile
    int ou = (t >> 3) * 2, kq = (t & 7) * 4;
    float au[2][4];
#pragma unroll
    for (int i = 0; i < 2; i++) {
        float bi = S.BU[ou + i];
#pragma unroll
        for (int j = 0; j < 4; j++) au[i][j] = bi;
    }
#pragma unroll
    for (int c = 0; c < 8; c++) {
        float2 p = ld2(&S.Pu[c * 64 + ou]);
        float4 h = ld4(&S.Hml[c * 32 + kq]);
        au[0][0] += p.x * h.x; au[0][1] += p.x * h.y; au[0][2] += p.x * h.z; au[0][3] += p.x * h.w;
        au[1][0] += p.y * h.x; au[1][1] += p.y * h.y; au[1][2] += p.y * h.z; au[1][3] += p.y * h.w;
    }
#pragma unroll
    for (int c = 0; c < 64; c++) {
        float2 qv = ld2(&S.Qu[c * 64 + ou]);
        float4 uv = ld4(&S.UE[c * 32 + kq]);
        au[0][0] += qv.x * uv.x; au[0][1] += qv.x * uv.y; au[0][2] += qv.x * uv.z; au[0][3] += qv.x * uv.w;
        au[1][0] += qv.y * uv.x; au[1][1] += qv.y * uv.y; au[1][2] += qv.y * uv.z; au[1][3] += qv.y * uv.w;
    }
    __syncthreads();   // GEMM reads done; reuse AP/UE as raw relu output staging

#pragma unroll
    for (int i = 0; i < 4; i++)
        st4(&S.AP[(o0 + i) * 64 + l0],
            make_float4(fmaxf(acc[i][0], 0.f), fmaxf(acc[i][1], 0.f),
                        fmaxf(acc[i][2], 0.f), fmaxf(acc[i][3], 0.f)));
#pragma unroll
    for (int i = 0; i < 2; i++)
        st4(&S.UE[(ou + i) * 32 + kq],
            make_float4(fmaxf(au[i][0], 0.f), fmaxf(au[i][1], 0.f),
                        fmaxf(au[i][2], 0.f), fmaxf(au[i][3], 0.f)));
    __syncthreads();

    if (t < 64) {
        float s = 0.f, ss = 0.f;
        for (int j = 0; j < 64; j++) { float x = S.AP[t * 64 + ((t + j) & 63)]; s += x; ss += x * x; }
        atomicAdd(&g_stats[256 + t], s); atomicAdd(&g_stats[320 + t], ss);
        float su = 0.f, ssu = 0.f;
        for (int j = 0; j < 32; j++) { float x = S.UE[t * 32 + ((t + j) & 31)]; su += x; ssu += x * x; }
        atomicAdd(&g_stats[384 + t], su); atomicAdd(&g_stats[448 + t], ssu);
        g_U1m[(size_t)b * 64 + t] = su * (1.f / 32.f);
    }
    float4* dA = reinterpret_cast<float4*>(g_A1 + (size_t)b * 4096);
    const float4* sA4 = reinterpret_cast<const float4*>(S.AP);
    for (int i = t; i < 1024; i += 256) dA[i] = sA4[i];
}

// ---------------- K3a: output layer + per-k norm -> Phat ----------------
__global__ void __launch_bounds__(256) k3a_phat(const float* __restrict__ gamma,
                                                const float* __restrict__ beta) {
    __shared__ float sAP[4096];          // normalized layer1 AP [c][l]
    __shared__ float sQ[2048];           // [c][k]
    __shared__ float sPo[256];           // [c8][k]
    __shared__ float sHmk[512];
    __shared__ float sV[32 * 65];        // V[k][l], padded
    __shared__ float sMU[64], sB[32], sFac[32], sScA[64], sShA[64];
    int b = blockIdx.x, t = threadIdx.x;

    if (t < 64) {
        float m = g_stats[256 + t] * (1.f / 65536.f);
        float v = g_stats[320 + t] * (1.f / 65536.f) - m * m;
        float sc = gamma[64 + t] * rsqrtf(v + EPS);
        sScA[t] = sc; sShA[t] = beta[64 + t] - m * sc;
        float mu = g_stats[384 + t] * (1.f / 32768.f);
        float vu = g_stats[448 + t] * (1.f / 32768.f) - mu * mu;
        float su = gamma[64 + t] * rsqrtf(vu + EPS);
        float sh = beta[64 + t] - mu * su;
        sMU[t] = g_U1m[(size_t)b * 64 + t] * su + sh;   // mean of BN'd UE1
    }
    for (int i = t; i < 2048; i += 256) sQ[i] = g_TQo[i];
    sPo[t] = g_TPo[t];
    for (int i = t; i < 512; i += 256) sHmk[i] = g_Hmk[(size_t)b * 512 + i];
    __syncthreads();
    for (int i = t; i < 4096; i += 256) {
        int c = i >> 6;
        sAP[i] = g_A1[(size_t)b * 4096 + i] * sScA[c] + sShA[c];
    }
    __syncthreads();
    if (t < 32) {
        const float* q2 = (const float*)0;  // placeholder removed below
        (void)q2;
    }
    if (t < 32) {
        // sB[k] = 2 * Qs_out[1][k] . sMU  — Qs_out[1] passed via g? use global Qo raw:
    }
    __syncthreads();
    // NOTE: bias computed below with raw Qo passed through constant path
    // (handled in k3a_bias inline — see launch wrapper)
    // -- replaced: compute here using __ldg on global pointer stored in sB via second kernel param
    // GEMM 32(k) x 64(l) x 72: thread tile 4(k) x 2(l)
    int ko = (t >> 5) * 4, lo = (t & 31) * 2;
    float acc[4][2];
#pragma unroll
    for (int i = 0; i < 4; i++) { acc[i][0] = sB[ko + i]; acc[i][1] = sB[ko + i]; }
#pragma unroll
    for (int c = 0; c < 8; c++) {
        float4 p = ld4(&sPo[c * 32 + ko]);
        float h0 = sHmk[c * 64 + lo], h1 = sHmk[c * 64 + lo + 1];
        acc[0][0] += p.x * h0; acc[0][1] += p.x * h1;
        acc[1][0] += p.y * h0; acc[1][1] += p.y * h1;
        acc[2][0] += p.z * h0; acc[2][1] += p.z * h1;
        acc[3][0] += p.w * h0; acc[3][1] += p.w * h1;
    }
#pragma unroll
    for (int c = 0; c < 64; c++) {
        float4 qv = ld4(&sQ[c * 32 + ko]);
        float2 a = ld2(&sAP[c * 64 + lo]);
        acc[0][0] += qv.x * a.x; acc[0][1] += qv.x * a.y;
        acc[1][0] += qv.y * a.x; acc[1][1] += qv.y * a.y;
        acc[2][0] += qv.z * a.x; acc[2][1] += qv.z * a.y;
        acc[3][0] += qv.w * a.x; acc[3][1] += qv.w * a.y;
    }
#pragma unroll
    for (int i = 0; i < 4; i++) {
        sV[(ko + i) * 65 + lo] = acc[i][0];
        sV[(ko + i) * 65 + lo + 1] = acc[i][1];
    }
    __syncthreads();
    if (t < 32) {
        float ss = 0.f;
        for (int j = 0; j < 64; j++) { float x = sV[t * 65 + ((t + j) & 63)]; ss += x * x; }
        sFac[t] = 8.f * rsqrtf(ss);                   // sqrt(L)=8
    }
    __syncthreads();
    for (int i = t; i < 2048; i += 256) {
        int l = i >> 5, k = i & 31;
        g_Phat[(size_t)b * 2048 + i] = sV[k * 65 + l] * sFac[k];
    }
}

// bias needs raw Qo; fold into k3a via a wrapper kernel variant taking Qo:
__global__ void __launch_bounds__(256) k3a_full(const float* __restrict__ Qo,
                                                const float* __restrict__ gamma,
                                                const float* __restrict__ beta) {
    __shared__ float sAP[4096];
    __shared__ float sQ[2048];
    __shared__ float sPo[256];
    __shared__ float sHmk[512];
    __shared__ float sV[32 * 65];
    __shared__ float sMU[64], sB[32], sFac[32], sScA[64], sShA[64];
    int b = blockIdx.x, t = threadIdx.x;

    if (t < 64) {
        float m = g_stats[256 + t] * (1.f / 65536.f);
        float v = g_stats[320 + t] * (1.f / 65536.f) - m * m;
        float sc = gamma[64 + t] * rsqrtf(v + EPS);
        sScA[t] = sc; sShA[t] = beta[64 + t] - m * sc;
        float mu = g_stats[384 + t] * (1.f / 32768.f);
        float vu = g_stats[448 + t] * (1.f / 32768.f) - mu * mu;
        float su = gamma[64 + t] * rsqrtf(vu + EPS);
        float sh = beta[64 + t] - mu * su;
        sMU[t] = g_U1m[(size_t)b * 64 + t] * su + sh;
    }
    for (int i = t; i < 2048; i += 256) sQ[i] = g_TQo[i];
    sPo[t] = g_TPo[t];
    for (int i = t; i < 512; i += 256) sHmk[i] = g_Hmk[(size_t)b * 512 + i];
    __syncthreads();
    for (int i = t; i < 4096; i += 256) {
        int c = i >> 6;
        sAP[i] = g_A1[(size_t)b * 4096 + i] * sScA[c] + sShA[c];
    }
    __syncthreads();
    if (t < 32) {
        const float* q2 = Qo + 2048 + t * 64;         // Qs_out[1]
        float s = 0.f;
        for (int c = 0; c < 64; c++) s += q2[c] * sMU[c];
        sB[t] = 2.f * s;
    }
    __syncthreads();

    int ko = (t >> 5) * 4, lo = (t & 31) * 2;
    float acc[4][2];
#pragma unroll
    for (int i = 0; i < 4; i++) { acc[i][0] = sB[ko + i]; acc[i][1] = sB[ko + i]; }
#pragma unroll
    for (int c = 0; c < 8; c++) {
        float4 p = ld4(&sPo[c * 32 + ko]);
        float h0 = sHmk[c * 64 + lo], h1 = sHmk[c * 64 + lo + 1];
        acc[0][0] += p.x * h0; acc[0][1] += p.x * h1;
        acc[1][0] += p.y * h0; acc[1][1] += p.y * h1;
        acc[2][0] += p.z * h0; acc[2][1] += p.z * h1;
        acc[3][0] += p.w * h0; acc[3][1] += p.w * h1;
    }
#pragma unroll
    for (int c = 0; c < 64; c++) {
        float4 qv = ld4(&sQ[c * 32 + ko]);
        float2 a = ld2(&sAP[c * 64 + lo]);
        acc[0][0] += qv.x * a.x; acc[0][1] += qv.x * a.y;
        acc[1][0] += qv.y * a.x; acc[1][1] += qv.y * a.y;
        acc[2][0] += qv.z * a.x; acc[2][1] += qv.z * a.y;
        acc[3][0] += qv.w * a.x; acc[3][1] += qv.w * a.y;
    }
#pragma unroll
    for (int i = 0; i < 4; i++) {
        sV[(ko + i) * 65 + lo] = acc[i][0];
        sV[(ko + i) * 65 + lo + 1] = acc[i][1];
    }
    __syncthreads();
    if (t < 32) {
        float ss = 0.f;
        for (int j = 0; j < 64; j++) { float x = sV[t * 65 + ((t + j) & 63)]; ss += x * x; }
        sFac[t] = 8.f * rsqrtf(ss);
    }
    __syncthreads();
    for (int i = t; i < 2048; i += 256) {
        int l = i >> 5, k = i & 31;
        g_Phat[(size_t)b * 2048 + i] = sV[k * 65 + l] * sFac[k];
    }
}

// ---------------- K3b: pure streaming out = Vhat * Phat ----------------
__global__ void __launch_bounds__(256) k3b_stream(const float* __restrict__ Vh,
                                                  float* __restrict__ out) {
    int idx = blockIdx.x * 256 + threadIdx.x;
    const float4* v4 = reinterpret_cast<const float4*>(Vh);
    float4* o4 = reinterpret_cast<float4*>(out);
#pragma unroll
    for (int it = 0; it < 4; it++) {
        int i = idx + it * 524288;
        float p = g_Phat[i];
        float4 v = v4[i];
        v.x *= p; v.y *= p; v.z *= p; v.w *= p;
        o4[i] = v;
    }
}

// ---------------- host ----------------
extern "C" void kernel_launch(void* const* d_in, const int* in_sizes, int n_in,
                              void* d_out, int out_size) {
    (void)in_sizes; (void)n_in; (void)out_size;
    const float* Hr = (const float*)d_in[0];
    const float* Hi = (const float*)d_in[1];
    const float* Vh = (const float*)d_in[2];
    const float* Qh = (const float*)d_in[3];
    const float* Ph = (const float*)d_in[4];
    const float* Qo = (const float*)d_in[5];
    const float* Po = (const float*)d_in[6];
    const float* gamma = (const float*)d_in[7];
    const float* beta = (const float*)d_in[8];

    static int attr_done = 0;
    if (!attr_done) {
        cudaFuncSetAttribute(k1_l0, cudaFuncAttributeMaxDynamicSharedMemorySize, (int)sizeof(SK1));
        cudaFuncSetAttribute(k2_l1, cudaFuncAttributeMaxDynamicSharedMemorySize, (int)sizeof(SK2));
        attr_done = 1;
    }

    k0_prep<<<1, 256>>>(Qh, Ph, Qo, Po);
    k1_l0<<<1024, 256, sizeof(SK1)>>>(Hr, Hi, Ph);
    k2_l1<<<1024, 256, sizeof(SK2)>>>(Qh, Ph, gamma, beta);
    k3a_full<<<1024, 256>>>(Qo, gamma, beta);
    k3b_stream<<<2048, 256>>>(Vh, (float*)d_out);
}

// round 4
// speedup vs baseline: 1.4627x; 1.2691x over previous
#include <cuda_runtime.h>

#define EPS 1e-5f

// ---------------- device scratch ----------------
__device__ float g_Hmk[1024 * 512];    // [b][c:8][l:64]
__device__ float g_Hml[1024 * 256];    // [b][c:8][k:32]
__device__ float g_A1[1024 * 4096];    // layer1 AP post-relu raw [b][o:64][l:64]
__device__ float g_U1m[1024 * 64];     // mean over k of layer1 UE post-relu raw [b][c:64]
__device__ float g_Phat[1024 * 2048];  // [b][l:64][k:32]
__device__ float g_stats[512];         // L0: apS,apSS,ueS,ueSS @0,64,128,192; L1 @256..
__device__ float g_TQa[4096];          // 2*Qh1[0]^T [c][o]
__device__ float g_TQu[4096];          // 2*Qh1[2]^T
__device__ float g_TQ2a[4096];         // 2*Qh1[1]^T [c][o]
__device__ float g_TQ2u[4096];         // 2*Qh1[3]^T
__device__ float g_TPa[512];           // 0.1*Ph1[0]^T [c:8][o:64]
__device__ float g_TPu[512];
__device__ float g_TQo[2048];          // 2*Qo[0]^T [c:64][k:32]
__device__ float g_TQo2[2048];         // 2*Qo[1]^T [c:64][k:32]
__device__ float g_TPo[256];           // 0.1*Po[0]^T [c:8][k:32]

static __device__ __forceinline__ float4 ld4(const float* p) { return *reinterpret_cast<const float4*>(p); }
static __device__ __forceinline__ float2 ld2(const float* p) { return *reinterpret_cast<const float2*>(p); }
static __device__ __forceinline__ void st4(float* p, float4 v) { *reinterpret_cast<float4*>(p) = v; }

// ---------------- K0: zero stats + transpose/pre-scale weights ----------------
__global__ void __launch_bounds__(256) k0_prep(const float* __restrict__ Qh,
                                               const float* __restrict__ Ph,
                                               const float* __restrict__ Qo,
                                               const float* __restrict__ Po) {
    int t = threadIdx.x;
    for (int i = t; i < 512; i += 256) g_stats[i] = 0.f;
    for (int i = t; i < 4096; i += 256) {
        int c = i >> 6, o = i & 63;
        g_TQa[i]  = 2.f * Qh[4 * 4096 + o * 64 + c];   // Qs_hidden[1][0]
        g_TQ2a[i] = 2.f * Qh[5 * 4096 + o * 64 + c];   // Qs_hidden[1][1]
        g_TQu[i]  = 2.f * Qh[6 * 4096 + o * 64 + c];   // Qs_hidden[1][2]
        g_TQ2u[i] = 2.f * Qh[7 * 4096 + o * 64 + c];   // Qs_hidden[1][3]
    }
    for (int i = t; i < 512; i += 256) {
        int c = i >> 6, o = i & 63;
        g_TPa[i] = 0.1f * Ph[1024 + o * 8 + c];        // Ps_hidden[1][0]
        g_TPu[i] = 0.1f * Ph[1536 + o * 8 + c];        // Ps_hidden[1][1]
    }
    for (int i = t; i < 2048; i += 256) {
        int c = i >> 5, k = i & 31;
        g_TQo[i]  = 2.f * Qo[k * 64 + c];              // Qs_out[0]
        g_TQo2[i] = 2.f * Qo[2048 + k * 64 + c];       // Qs_out[1]
    }
    { int c = t >> 5, k = t & 31; g_TPo[t] = 0.1f * Po[k * 8 + c]; }  // Ps_out[0]
}

// ---------------- K1: single pass over H -> Hmk/Hml + layer0 stats ----------------
struct SK1 {
    float S[8][64 * 33];    // [c][l*33+k]
    float Hmk[512];
    float Hml[256];
};

__global__ void __launch_bounds__(256) k1_l0(const float* __restrict__ Hr,
                                             const float* __restrict__ Hi,
                                             const float* __restrict__ Ph) {
    extern __shared__ __align__(16) char sraw1[];
    SK1& S = *reinterpret_cast<SK1*>(sraw1);
    int b = blockIdx.x, t = threadIdx.x, w = t >> 5, lane = t & 31;

    const float4* hr4 = reinterpret_cast<const float4*>(Hr) + (size_t)b * 2048;
    const float4* hi4 = reinterpret_cast<const float4*>(Hi) + (size_t)b * 2048;
#pragma unroll
    for (int i = 0; i < 8; i++) {
        int l = i * 8 + w;
        float4 r = hr4[l * 32 + lane];
        float4 m = hi4[l * 32 + lane];
        int base = l * 33 + lane;
        S.S[0][base] = r.x; S.S[1][base] = r.y; S.S[2][base] = r.z; S.S[3][base] = r.w;
        S.S[4][base] = m.x; S.S[5][base] = m.y; S.S[6][base] = m.z; S.S[7][base] = m.w;
    }
    __syncthreads();

#pragma unroll
    for (int p = 0; p < 2; p++) {
        int idx = t + p * 256;
        int c = idx >> 6, l = idx & 63;
        float s = 0.f;
#pragma unroll
        for (int k = 0; k < 32; k++) s += S.S[c][l * 33 + k];
        float v = s * (1.f / 32.f);
        S.Hmk[idx] = v;
        g_Hmk[(size_t)b * 512 + idx] = v;
    }
    {
        int c = t >> 5, k = t & 31;
        float s = 0.f;
#pragma unroll
        for (int l = 0; l < 64; l++) s += S.S[c][l * 33 + k];
        float v = s * (1.f / 64.f);
        S.Hml[t] = v;
        g_Hml[(size_t)b * 256 + t] = v;
    }
    __syncthreads();

    // layer0 stats (A inputs zero => relu(0.1*P0 @ Hmean))
    int o = t >> 2, q = t & 3;
    float pa[8], pu[8];
#pragma unroll
    for (int c = 0; c < 8; c++) {
        pa[c] = 0.1f * Ph[o * 8 + c];
        pu[c] = 0.1f * Ph[512 + o * 8 + c];
    }
    float ps = 0.f, pss = 0.f;
#pragma unroll
    for (int j = 0; j < 16; j++) {
        int l = q * 16 + j;
        float v = 0.f;
#pragma unroll
        for (int c = 0; c < 8; c++) v += pa[c] * S.Hmk[c * 64 + l];
        v = fmaxf(v, 0.f);
        ps += v; pss += v * v;
    }
    ps += __shfl_xor_sync(0xffffffffu, ps, 1);  ps += __shfl_xor_sync(0xffffffffu, ps, 2);
    pss += __shfl_xor_sync(0xffffffffu, pss, 1); pss += __shfl_xor_sync(0xffffffffu, pss, 2);
    if (q == 0) { atomicAdd(&g_stats[o], ps); atomicAdd(&g_stats[64 + o], pss); }

    float us = 0.f, uss = 0.f;
#pragma unroll
    for (int j = 0; j < 8; j++) {
        int k = q * 8 + j;
        float v = 0.f;
#pragma unroll
        for (int c = 0; c < 8; c++) v += pu[c] * S.Hml[c * 32 + k];
        v = fmaxf(v, 0.f);
        us += v; uss += v * v;
    }
    us += __shfl_xor_sync(0xffffffffu, us, 1);  us += __shfl_xor_sync(0xffffffffu, us, 2);
    uss += __shfl_xor_sync(0xffffffffu, uss, 1); uss += __shfl_xor_sync(0xffffffffu, uss, 2);
    if (q == 0) { atomicAdd(&g_stats[128 + o], us); atomicAdd(&g_stats[192 + o], uss); }
}

// ---------------- K2: recompute layer0 (lazy BN), layer1 GEMMs, relu, stats ----------------
struct __align__(16) SK2 {
    float AP[4096], UE[2048];
    float Pa[512], Pu[512], P0a[512], P0u[512];
    float Hmk[512], Hml[256];
    float Part[8 * 64];                 // bias partials (2 x 4 x 64)
    float ScA[64], ShA[64], ScU[64], ShU[64];
    float MA[64], MU[64], BA[64], BU[64];
};

__global__ void __launch_bounds__(256) k2_l1(const float* __restrict__ gamma,
                                             const float* __restrict__ beta) {
    extern __shared__ __align__(16) char sraw[];
    SK2& S = *reinterpret_cast<SK2*>(sraw);
    int b = blockIdx.x, t = threadIdx.x;

    if (t < 64) {
        float m = g_stats[t] * (1.f / 65536.f);
        float v = g_stats[64 + t] * (1.f / 65536.f) - m * m;
        float sc = gamma[t] * rsqrtf(v + EPS);
        S.ScA[t] = sc; S.ShA[t] = beta[t] - m * sc;
        float mu = g_stats[128 + t] * (1.f / 32768.f);
        float vu = g_stats[192 + t] * (1.f / 32768.f) - mu * mu;
        float su = gamma[t] * rsqrtf(vu + EPS);
        S.ScU[t] = su; S.ShU[t] = beta[t] - mu * su;
    }
    for (int i = t; i < 512; i += 256) {
        S.Pa[i] = g_TPa[i]; S.Pu[i] = g_TPu[i];
        S.P0a[i] = g_TPa[i] * 0.f;   // placeholder overwritten below
    }
    // P0 from K1's helper path: recompute from transposed? P0 is layer-0 weights (not transposed);
    // load directly (small, L2-cached).
    __syncthreads();

    // recompute normalized layer0 outputs (P0 weights read per-thread from global, cached)
    {
        int l = t & 63, og = t >> 6;
#pragma unroll
        for (int j = 0; j < 16; j++) {
            int o = og * 16 + j;
            float r = 0.f;
#pragma unroll
            for (int c = 0; c < 8; c++) r += S.P0a[o * 8 + c] * S.Hmk[c * 64 + l];
            S.AP[o * 64 + l] = fmaxf(r, 0.f) * S.ScA[o] + S.ShA[o];
        }
    }
    __syncthreads();
}

// NOTE: k2 is implemented as k2_full below; the stub above is unused.
__global__ void __launch_bounds__(256) k2_full(const float* __restrict__ Ph,
                                               const float* __restrict__ gamma,
                                               const float* __restrict__ beta) {
    extern __shared__ __align__(16) char sraw[];
    SK2& S = *reinterpret_cast<SK2*>(sraw);
    int b = blockIdx.x, t = threadIdx.x;

    if (t < 64) {
        float m = g_stats[t] * (1.f / 65536.f);
        float v = g_stats[64 + t] * (1.f / 65536.f) - m * m;
        float sc = gamma[t] * rsqrtf(v + EPS);
        S.ScA[t] = sc; S.ShA[t] = beta[t] - m * sc;
        float mu = g_stats[128 + t] * (1.f / 32768.f);
        float vu = g_stats[192 + t] * (1.f / 32768.f) - mu * mu;
        float su = gamma[t] * rsqrtf(vu + EPS);
        S.ScU[t] = su; S.ShU[t] = beta[t] - mu * su;
    }
    for (int i = t; i < 512; i += 256) {
        S.Pa[i] = g_TPa[i]; S.Pu[i] = g_TPu[i];
        S.P0a[i] = 0.1f * Ph[i]; S.P0u[i] = 0.1f * Ph[512 + i];
        S.Hmk[i] = g_Hmk[(size_t)b * 512 + i];
    }
    S.Hml[t] = g_Hml[(size_t)b * 256 + t];
    __syncthreads();

    // recompute normalized layer0 outputs
    {
        int l = t & 63, og = t >> 6;
#pragma unroll
        for (int j = 0; j < 16; j++) {
            int o = og * 16 + j;
            float r = 0.f;
#pragma unroll
            for (int c = 0; c < 8; c++) r += S.P0a[o * 8 + c] * S.Hmk[c * 64 + l];
            S.AP[o * 64 + l] = fmaxf(r, 0.f) * S.ScA[o] + S.ShA[o];
        }
        int k = t & 31, og2 = t >> 5;
#pragma unroll
        for (int j = 0; j < 8; j++) {
            int o = og2 * 8 + j;
            float r = 0.f;
#pragma unroll
            for (int c = 0; c < 8; c++) r += S.P0u[o * 8 + c] * S.Hml[c * 32 + k];
            S.UE[o * 32 + k] = fmaxf(r, 0.f) * S.ScU[o] + S.ShU[o];
        }
    }
    __syncthreads();

    // means: MA over l (16 l's per thread, 4-lane shuffle), MU over k (8 k's per thread)
    {
        int o = t >> 2, q = t & 3;
        float s = 0.f;
#pragma unroll
        for (int j = 0; j < 16; j++) s += S.AP[o * 64 + q * 16 + ((o + j) & 15)];
        s += __shfl_xor_sync(0xffffffffu, s, 1); s += __shfl_xor_sync(0xffffffffu, s, 2);
        if (q == 0) S.MA[o] = s * (1.f / 64.f);
        float su = 0.f;
#pragma unroll
        for (int j = 0; j < 8; j++) su += S.UE[o * 32 + q * 8 + ((o + j) & 7)];
        su += __shfl_xor_sync(0xffffffffu, su, 1); su += __shfl_xor_sync(0xffffffffu, su, 2);
        if (q == 0) S.MU[o] = su * (1.f / 32.f);
    }
    __syncthreads();

    // bias: BA[o] = sum_c 2*Q2a^T[c][o]*MU[c]; coalesced global reads, 4 partials
    {
        int o = t & 63, g = t >> 6;
        float s = 0.f, su = 0.f;
#pragma unroll
        for (int j = 0; j < 16; j++) {
            int c = g * 16 + j;
            s  += g_TQ2a[c * 64 + o] * S.MU[c];
            su += g_TQ2u[c * 64 + o] * S.MA[c];
        }
        S.Part[g * 64 + o] = s;
        S.Part[256 + g * 64 + o] = su;
    }
    __syncthreads();
    if (t < 64) {
        S.BA[t] = S.Part[t] + S.Part[64 + t] + S.Part[128 + t] + S.Part[192 + t];
        S.BU[t] = S.Part[256 + t] + S.Part[320 + t] + S.Part[384 + t] + S.Part[448 + t];
    }
    __syncthreads();

    // AP GEMM: 4(o) x 4(l) tile; Q weights from global (L1-resident broadcast)
    int o0 = (t >> 4) * 4, l0 = (t & 15) * 4;
    float acc[4][4];
#pragma unroll
    for (int i = 0; i < 4; i++) {
        float bi = S.BA[o0 + i];
#pragma unroll
        for (int j = 0; j < 4; j++) acc[i][j] = bi;
    }
#pragma unroll
    for (int c = 0; c < 8; c++) {
        float4 p = ld4(&S.Pa[c * 64 + o0]);
        float4 h = ld4(&S.Hmk[c * 64 + l0]);
        acc[0][0] += p.x * h.x; acc[0][1] += p.x * h.y; acc[0][2] += p.x * h.z; acc[0][3] += p.x * h.w;
        acc[1][0] += p.y * h.x; acc[1][1] += p.y * h.y; acc[1][2] += p.y * h.z; acc[1][3] += p.y * h.w;
        acc[2][0] += p.z * h.x; acc[2][1] += p.z * h.y; acc[2][2] += p.z * h.z; acc[2][3] += p.z * h.w;
        acc[3][0] += p.w * h.x; acc[3][1] += p.w * h.y; acc[3][2] += p.w * h.z; acc[3][3] += p.w * h.w;
    }
#pragma unroll
    for (int c = 0; c < 64; c++) {
        float4 qv = ld4(&g_TQa[c * 64 + o0]);
        float4 av = ld4(&S.AP[c * 64 + l0]);
        acc[0][0] += qv.x * av.x; acc[0][1] += qv.x * av.y; acc[0][2] += qv.x * av.z; acc[0][3] += qv.x * av.w;
        acc[1][0] += qv.y * av.x; acc[1][1] += qv.y * av.y; acc[1][2] += qv.y * av.z; acc[1][3] += qv.y * av.w;
        acc[2][0] += qv.z * av.x; acc[2][1] += qv.z * av.y; acc[2][2] += qv.z * av.z; acc[2][3] += qv.z * av.w;
        acc[3][0] += qv.w * av.x; acc[3][1] += qv.w * av.y; acc[3][2] += qv.w * av.z; acc[3][3] += qv.w * av.w;
    }

    // UE GEMM: 2(o) x 4(k) tile
    int ou = (t >> 3) * 2, kq = (t & 7) * 4;
    float au[2][4];
#pragma unroll
    for (int i = 0; i < 2; i++) {
        float bi = S.BU[ou + i];
#pragma unroll
        for (int j = 0; j < 4; j++) au[i][j] = bi;
    }
#pragma unroll
    for (int c = 0; c < 8; c++) {
        float2 p = ld2(&S.Pu[c * 64 + ou]);
        float4 h = ld4(&S.Hml[c * 32 + kq]);
        au[0][0] += p.x * h.x; au[0][1] += p.x * h.y; au[0][2] += p.x * h.z; au[0][3] += p.x * h.w;
        au[1][0] += p.y * h.x; au[1][1] += p.y * h.y; au[1][2] += p.y * h.z; au[1][3] += p.y * h.w;
    }
#pragma unroll
    for (int c = 0; c < 64; c++) {
        float2 qv = ld2(&g_TQu[c * 64 + ou]);
        float4 uv = ld4(&S.UE[c * 32 + kq]);
        au[0][0] += qv.x * uv.x; au[0][1] += qv.x * uv.y; au[0][2] += qv.x * uv.z; au[0][3] += qv.x * uv.w;
        au[1][0] += qv.y * uv.x; au[1][1] += qv.y * uv.y; au[1][2] += qv.y * uv.z; au[1][3] += qv.y * uv.w;
    }
    __syncthreads();   // GEMM reads done; reuse AP/UE as raw relu output staging

#pragma unroll
    for (int i = 0; i < 4; i++)
        st4(&S.AP[(o0 + i) * 64 + l0],
            make_float4(fmaxf(acc[i][0], 0.f), fmaxf(acc[i][1], 0.f),
                        fmaxf(acc[i][2], 0.f), fmaxf(acc[i][3], 0.f)));
#pragma unroll
    for (int i = 0; i < 2; i++)
        st4(&S.UE[(ou + i) * 32 + kq],
            make_float4(fmaxf(au[i][0], 0.f), fmaxf(au[i][1], 0.f),
                        fmaxf(au[i][2], 0.f), fmaxf(au[i][3], 0.f)));
    __syncthreads();

    // layer1 stats: 4-lane shuffle groups + atomics
    {
        int o = t >> 2, q = t & 3;
        float s = 0.f, ss = 0.f;
#pragma unroll
        for (int j = 0; j < 16; j++) {
            float x = S.AP[o * 64 + q * 16 + ((o + j) & 15)];
            s += x; ss += x * x;
        }
        s += __shfl_xor_sync(0xffffffffu, s, 1);  s += __shfl_xor_sync(0xffffffffu, s, 2);
        ss += __shfl_xor_sync(0xffffffffu, ss, 1); ss += __shfl_xor_sync(0xffffffffu, ss, 2);
        if (q == 0) { atomicAdd(&g_stats[256 + o], s); atomicAdd(&g_stats[320 + o], ss); }
        float su = 0.f, ssu = 0.f;
#pragma unroll
        for (int j = 0; j < 8; j++) {
            float x = S.UE[o * 32 + q * 8 + ((o + j) & 7)];
            su += x; ssu += x * x;
        }
        su += __shfl_xor_sync(0xffffffffu, su, 1);  su += __shfl_xor_sync(0xffffffffu, su, 2);
        ssu += __shfl_xor_sync(0xffffffffu, ssu, 1); ssu += __shfl_xor_sync(0xffffffffu, ssu, 2);
        if (q == 0) {
            atomicAdd(&g_stats[384 + o], su); atomicAdd(&g_stats[448 + o], ssu);
            g_U1m[(size_t)b * 64 + o] = su * (1.f / 32.f);
        }
    }
    float4* dA = reinterpret_cast<float4*>(g_A1 + (size_t)b * 4096);
    const float4* sA4 = reinterpret_cast<const float4*>(S.AP);
    for (int i = t; i < 1024; i += 256) dA[i] = sA4[i];
}

// ---------------- K3a: output layer + per-k norm -> Phat ----------------
__global__ void __launch_bounds__(256) k3a_full(const float* __restrict__ gamma,
                                                const float* __restrict__ beta) {
    __shared__ float sAP[4096];          // normalized layer1 AP [c][l]
    __shared__ float sPo[256];           // [c8][k]
    __shared__ float sHmk[512];
    __shared__ float sV[32 * 65];
    __shared__ float sPb[8 * 32];        // bias partials
    __shared__ float sMU[64], sB[32], sFac[32], sScA[64], sShA[64];
    int b = blockIdx.x, t = threadIdx.x;

    // prefetch raw A1 into registers (hide DRAM latency behind setup)
    float a_raw[16];
#pragma unroll
    for (int j = 0; j < 16; j++) a_raw[j] = g_A1[(size_t)b * 4096 + t + j * 256];

    if (t < 64) {
        float m = g_stats[256 + t] * (1.f / 65536.f);
        float v = g_stats[320 + t] * (1.f / 65536.f) - m * m;
        float sc = gamma[64 + t] * rsqrtf(v + EPS);
        sScA[t] = sc; sShA[t] = beta[64 + t] - m * sc;
        float mu = g_stats[384 + t] * (1.f / 32768.f);
        float vu = g_stats[448 + t] * (1.f / 32768.f) - mu * mu;
        float su = gamma[64 + t] * rsqrtf(vu + EPS);
        float sh = beta[64 + t] - mu * su;
        sMU[t] = g_U1m[(size_t)b * 64 + t] * su + sh;
    }
    sPo[t] = g_TPo[t];
    for (int i = t; i < 512; i += 256) sHmk[i] = g_Hmk[(size_t)b * 512 + i];
    __syncthreads();

    // normalized AP to smem + bias partials (both only need phase-1 results)
#pragma unroll
    for (int j = 0; j < 16; j++) {
        int i = t + j * 256;
        int c = i >> 6;
        sAP[i] = a_raw[j] * sScA[c] + sShA[c];
    }
    {
        int k = t & 31, g = t >> 5;
        float s = 0.f;
#pragma unroll
        for (int j = 0; j < 8; j++) {
            int c = g * 8 + j;
            s += g_TQo2[c * 32 + k] * sMU[c];
        }
        sPb[g * 32 + k] = s;
    }
    __syncthreads();
    if (t < 32) {
        float s = 0.f;
#pragma unroll
        for (int g = 0; g < 8; g++) s += sPb[g * 32 + t];
        sB[t] = s;
    }
    __syncthreads();

    // GEMM 32(k) x 64(l) x 72: thread tile 4(k) x 2(l); Q from global
    int ko = (t >> 5) * 4, lo = (t & 31) * 2;
    float acc[4][2];
#pragma unroll
    for (int i = 0; i < 4; i++) { acc[i][0] = sB[ko + i]; acc[i][1] = sB[ko + i]; }
#pragma unroll
    for (int c = 0; c < 8; c++) {
        float4 p = ld4(&sPo[c * 32 + ko]);
        float h0 = sHmk[c * 64 + lo], h1 = sHmk[c * 64 + lo + 1];
        acc[0][0] += p.x * h0; acc[0][1] += p.x * h1;
        acc[1][0] += p.y * h0; acc[1][1] += p.y * h1;
        acc[2][0] += p.z * h0; acc[2][1] += p.z * h1;
        acc[3][0] += p.w * h0; acc[3][1] += p.w * h1;
    }
#pragma unroll
    for (int c = 0; c < 64; c++) {
        float4 qv = ld4(&g_TQo[c * 32 + ko]);
        float2 a = ld2(&sAP[c * 64 + lo]);
        acc[0][0] += qv.x * a.x; acc[0][1] += qv.x * a.y;
        acc[1][0] += qv.y * a.x; acc[1][1] += qv.y * a.y;
        acc[2][0] += qv.z * a.x; acc[2][1] += qv.z * a.y;
        acc[3][0] += qv.w * a.x; acc[3][1] += qv.w * a.y;
    }
#pragma unroll
    for (int i = 0; i < 4; i++) {
        sV[(ko + i) * 65 + lo] = acc[i][0];
        sV[(ko + i) * 65 + lo + 1] = acc[i][1];
    }
    __syncthreads();

    // norm: 8 lanes per k, shuffle reduce
    {
        int k = t >> 3, j = t & 7;
        float ss = 0.f;
#pragma unroll
        for (int i = 0; i < 8; i++) {
            float x = sV[k * 65 + j * 8 + i];
            ss += x * x;
        }
        ss += __shfl_xor_sync(0xffffffffu, ss, 1);
        ss += __shfl_xor_sync(0xffffffffu, ss, 2);
        ss += __shfl_xor_sync(0xffffffffu, ss, 4);
        if (j == 0) sFac[k] = 8.f * rsqrtf(ss);
    }
    __syncthreads();
    for (int i = t; i < 2048; i += 256) {
        int l = i >> 5, k = i & 31;
        g_Phat[(size_t)b * 2048 + i] = sV[k * 65 + l] * sFac[k];
    }
}

// ---------------- K3b: pure streaming out = Vhat * Phat ----------------
__global__ void __launch_bounds__(256) k3b_stream(const float* __restrict__ Vh,
                                                  float* __restrict__ out) {
    int idx = blockIdx.x * 256 + threadIdx.x;
    const float4* v4 = reinterpret_cast<const float4*>(Vh);
    float4* o4 = reinterpret_cast<float4*>(out);
#pragma unroll
    for (int it = 0; it < 4; it++) {
        int i = idx + it * 524288;
        float p = g_Phat[i];
        float4 v = v4[i];
        v.x *= p; v.y *= p; v.z *= p; v.w *= p;
        o4[i] = v;
    }
}

// ---------------- host ----------------
extern "C" void kernel_launch(void* const* d_in, const int* in_sizes, int n_in,
                              void* d_out, int out_size) {
    (void)in_sizes; (void)n_in; (void)out_size;
    const float* Hr = (const float*)d_in[0];
    const float* Hi = (const float*)d_in[1];
    const float* Vh = (const float*)d_in[2];
    const float* Qh = (const float*)d_in[3];
    const float* Ph = (const float*)d_in[4];
    const float* Qo = (const float*)d_in[5];
    const float* Po = (const float*)d_in[6];
    const float* gamma = (const float*)d_in[7];
    const float* beta = (const float*)d_in[8];

    static int attr_done = 0;
    if (!attr_done) {
        cudaFuncSetAttribute(k1_l0, cudaFuncAttributeMaxDynamicSharedMemorySize, (int)sizeof(SK1));
        cudaFuncSetAttribute(k2_full, cudaFuncAttributeMaxDynamicSharedMemorySize, (int)sizeof(SK2));
        attr_done = 1;
    }

    k0_prep<<<1, 256>>>(Qh, Ph, Qo, Po);
    k1_l0<<<1024, 256, sizeof(SK1)>>>(Hr, Hi, Ph);
    k2_full<<<1024, 256, sizeof(SK2)>>>(Ph, gamma, beta);
    k3a_full<<<1024, 256>>>(gamma, beta);
    k3b_stream<<<2048, 256>>>(Vh, (float*)d_out);
}

// round 5
// speedup vs baseline: 1.5996x; 1.0936x over previous
#include <cuda_runtime.h>

#define EPS 1e-5f

// ---------------- device scratch ----------------
__device__ float g_Hmk[1024 * 512];    // [b][c:8][l:64]
__device__ float g_Hml[1024 * 256];    // [b][c:8][k:32]
__device__ float g_A1[1024 * 4096];    // layer1 AP post-relu raw [b][o:64][l:64]
__device__ float g_U1m[1024 * 64];     // mean over k of layer1 UE post-relu raw [b][c:64]
__device__ float g_stats[512];         // L0: apS,apSS,ueS,ueSS @0,64,128,192; L1 @256..
__device__ float g_TQa[4096];          // 2*Qh1[0]^T [c][o]
__device__ float g_TQu[4096];          // 2*Qh1[2]^T
__device__ float g_TQ2a[4096];         // 2*Qh1[1]^T [c][o]
__device__ float g_TQ2u[4096];         // 2*Qh1[3]^T
__device__ float g_TPa[512];           // 0.1*Ph1[0]^T [c:8][o:64]
__device__ float g_TPu[512];
__device__ float g_TQo[2048];          // 2*Qo[0]^T [c:64][k:32]
__device__ float g_TQo2[2048];         // 2*Qo[1]^T [c:64][k:32]
__device__ float g_TPo[256];           // 0.1*Po[0]^T [c:8][k:32]

static __device__ __forceinline__ float4 ld4(const float* p) { return *reinterpret_cast<const float4*>(p); }
static __device__ __forceinline__ float2 ld2(const float* p) { return *reinterpret_cast<const float2*>(p); }
static __device__ __forceinline__ void st4(float* p, float4 v) { *reinterpret_cast<float4*>(p) = v; }

// ---------------- K0 (16 blocks): zero stats + transpose/pre-scale weights ----------------
__global__ void __launch_bounds__(256) k0_prep(const float* __restrict__ Qh,
                                               const float* __restrict__ Ph,
                                               const float* __restrict__ Qo,
                                               const float* __restrict__ Po) {
    int gt = blockIdx.x * 256 + threadIdx.x;   // 0..4095
    if (gt < 512) g_stats[gt] = 0.f;
    {
        int c = gt >> 6, o = gt & 63;
        g_TQa[gt]  = 2.f * Qh[4 * 4096 + o * 64 + c];   // Qs_hidden[1][0]
        g_TQ2a[gt] = 2.f * Qh[5 * 4096 + o * 64 + c];   // Qs_hidden[1][1]
        g_TQu[gt]  = 2.f * Qh[6 * 4096 + o * 64 + c];   // Qs_hidden[1][2]
        g_TQ2u[gt] = 2.f * Qh[7 * 4096 + o * 64 + c];   // Qs_hidden[1][3]
    }
    if (gt < 512) {
        int c = gt >> 6, o = gt & 63;
        g_TPa[gt] = 0.1f * Ph[1024 + o * 8 + c];        // Ps_hidden[1][0]
        g_TPu[gt] = 0.1f * Ph[1536 + o * 8 + c];        // Ps_hidden[1][1]
    }
    if (gt < 2048) {
        int c = gt >> 5, k = gt & 31;
        g_TQo[gt]  = 2.f * Qo[k * 64 + c];              // Qs_out[0]
        g_TQo2[gt] = 2.f * Qo[2048 + k * 64 + c];       // Qs_out[1]
    }
    if (gt < 256) {
        int c = gt >> 5, k = gt & 31;
        g_TPo[gt] = 0.1f * Po[k * 8 + c];               // Ps_out[0]
    }
}

// ---------------- K1: single pass over H -> Hmk/Hml + layer0 stats ----------------
struct SK1 {
    float S[8][64 * 33];    // [c][l*33+k]
    float Hmk[512];
    float Hml[256];
};

__global__ void __launch_bounds__(256) k1_l0(const float* __restrict__ Hr,
                                             const float* __restrict__ Hi,
                                             const float* __restrict__ Ph) {
    extern __shared__ __align__(16) char sraw1[];
    SK1& S = *reinterpret_cast<SK1*>(sraw1);
    int b = blockIdx.x, t = threadIdx.x, w = t >> 5, lane = t & 31;

    const float4* hr4 = reinterpret_cast<const float4*>(Hr) + (size_t)b * 2048;
    const float4* hi4 = reinterpret_cast<const float4*>(Hi) + (size_t)b * 2048;
#pragma unroll
    for (int i = 0; i < 8; i++) {
        int l = i * 8 + w;
        float4 r = hr4[l * 32 + lane];
        float4 m = hi4[l * 32 + lane];
        int base = l * 33 + lane;
        S.S[0][base] = r.x; S.S[1][base] = r.y; S.S[2][base] = r.z; S.S[3][base] = r.w;
        S.S[4][base] = m.x; S.S[5][base] = m.y; S.S[6][base] = m.z; S.S[7][base] = m.w;
    }
    __syncthreads();

#pragma unroll
    for (int p = 0; p < 2; p++) {
        int idx = t + p * 256;
        int c = idx >> 6, l = idx & 63;
        float s = 0.f;
#pragma unroll
        for (int k = 0; k < 32; k++) s += S.S[c][l * 33 + k];
        float v = s * (1.f / 32.f);
        S.Hmk[idx] = v;
        g_Hmk[(size_t)b * 512 + idx] = v;
    }
    {
        int c = t >> 5, k = t & 31;
        float s = 0.f;
#pragma unroll
        for (int l = 0; l < 64; l++) s += S.S[c][l * 33 + k];
        float v = s * (1.f / 64.f);
        S.Hml[t] = v;
        g_Hml[(size_t)b * 256 + t] = v;
    }
    __syncthreads();

    // layer0 stats (A inputs zero => relu(0.1*P0 @ Hmean))
    int o = t >> 2, q = t & 3;
    float pa[8], pu[8];
#pragma unroll
    for (int c = 0; c < 8; c++) {
        pa[c] = 0.1f * Ph[o * 8 + c];
        pu[c] = 0.1f * Ph[512 + o * 8 + c];
    }
    float ps = 0.f, pss = 0.f;
#pragma unroll
    for (int j = 0; j < 16; j++) {
        int l = q * 16 + j;
        float v = 0.f;
#pragma unroll
        for (int c = 0; c < 8; c++) v += pa[c] * S.Hmk[c * 64 + l];
        v = fmaxf(v, 0.f);
        ps += v; pss += v * v;
    }
    ps += __shfl_xor_sync(0xffffffffu, ps, 1);  ps += __shfl_xor_sync(0xffffffffu, ps, 2);
    pss += __shfl_xor_sync(0xffffffffu, pss, 1); pss += __shfl_xor_sync(0xffffffffu, pss, 2);
    if (q == 0) { atomicAdd(&g_stats[o], ps); atomicAdd(&g_stats[64 + o], pss); }

    float us = 0.f, uss = 0.f;
#pragma unroll
    for (int j = 0; j < 8; j++) {
        int k = q * 8 + j;
        float v = 0.f;
#pragma unroll
        for (int c = 0; c < 8; c++) v += pu[c] * S.Hml[c * 32 + k];
        v = fmaxf(v, 0.f);
        us += v; uss += v * v;
    }
    us += __shfl_xor_sync(0xffffffffu, us, 1);  us += __shfl_xor_sync(0xffffffffu, us, 2);
    uss += __shfl_xor_sync(0xffffffffu, uss, 1); uss += __shfl_xor_sync(0xffffffffu, uss, 2);
    if (q == 0) { atomicAdd(&g_stats[128 + o], us); atomicAdd(&g_stats[192 + o], uss); }
}

// ---------------- K2: recompute layer0 (lazy BN), layer1 GEMMs, relu, stats ----------------
struct __align__(16) SK2 {
    float AP[4096], UE[2048];
    float Pa[512], Pu[512], P0a[512], P0u[512];
    float Hmk[512], Hml[256];
    float Part[8 * 64];
    float ScA[64], ShA[64], ScU[64], ShU[64];
    float MA[64], MU[64], BA[64], BU[64];
};

__global__ void __launch_bounds__(256) k2_full(const float* __restrict__ Ph,
                                               const float* __restrict__ gamma,
                                               const float* __restrict__ beta) {
    extern __shared__ __align__(16) char sraw[];
    SK2& S = *reinterpret_cast<SK2*>(sraw);
    int b = blockIdx.x, t = threadIdx.x;

    if (t < 64) {
        float m = g_stats[t] * (1.f / 65536.f);
        float v = g_stats[64 + t] * (1.f / 65536.f) - m * m;
        float sc = gamma[t] * rsqrtf(v + EPS);
        S.ScA[t] = sc; S.ShA[t] = beta[t] - m * sc;
        float mu = g_stats[128 + t] * (1.f / 32768.f);
        float vu = g_stats[192 + t] * (1.f / 32768.f) - mu * mu;
        float su = gamma[t] * rsqrtf(vu + EPS);
        S.ScU[t] = su; S.ShU[t] = beta[t] - mu * su;
    }
    for (int i = t; i < 512; i += 256) {
        S.Pa[i] = g_TPa[i]; S.Pu[i] = g_TPu[i];
        S.P0a[i] = 0.1f * Ph[i]; S.P0u[i] = 0.1f * Ph[512 + i];
        S.Hmk[i] = g_Hmk[(size_t)b * 512 + i];
    }
    S.Hml[t] = g_Hml[(size_t)b * 256 + t];
    __syncthreads();

    // recompute normalized layer0 outputs
    {
        int l = t & 63, og = t >> 6;
#pragma unroll
        for (int j = 0; j < 16; j++) {
            int o = og * 16 + j;
            float r = 0.f;
#pragma unroll
            for (int c = 0; c < 8; c++) r += S.P0a[o * 8 + c] * S.Hmk[c * 64 + l];
            S.AP[o * 64 + l] = fmaxf(r, 0.f) * S.ScA[o] + S.ShA[o];
        }
        int k = t & 31, og2 = t >> 5;
#pragma unroll
        for (int j = 0; j < 8; j++) {
            int o = og2 * 8 + j;
            float r = 0.f;
#pragma unroll
            for (int c = 0; c < 8; c++) r += S.P0u[o * 8 + c] * S.Hml[c * 32 + k];
            S.UE[o * 32 + k] = fmaxf(r, 0.f) * S.ScU[o] + S.ShU[o];
        }
    }
    __syncthreads();

    // means over l / k (4-lane shuffle groups)
    {
        int o = t >> 2, q = t & 3;
        float s = 0.f;
#pragma unroll
        for (int j = 0; j < 16; j++) s += S.AP[o * 64 + q * 16 + ((o + j) & 15)];
        s += __shfl_xor_sync(0xffffffffu, s, 1); s += __shfl_xor_sync(0xffffffffu, s, 2);
        if (q == 0) S.MA[o] = s * (1.f / 64.f);
        float su = 0.f;
#pragma unroll
        for (int j = 0; j < 8; j++) su += S.UE[o * 32 + q * 8 + ((o + j) & 7)];
        su += __shfl_xor_sync(0xffffffffu, su, 1); su += __shfl_xor_sync(0xffffffffu, su, 2);
        if (q == 0) S.MU[o] = su * (1.f / 32.f);
    }
    __syncthreads();

    // bias partials: coalesced global reads, 4 partials per channel
    {
        int o = t & 63, g = t >> 6;
        float s = 0.f, su = 0.f;
#pragma unroll
        for (int j = 0; j < 16; j++) {
            int c = g * 16 + j;
            s  += g_TQ2a[c * 64 + o] * S.MU[c];
            su += g_TQ2u[c * 64 + o] * S.MA[c];
        }
        S.Part[g * 64 + o] = s;
        S.Part[256 + g * 64 + o] = su;
    }
    __syncthreads();
    if (t < 64) {
        S.BA[t] = S.Part[t] + S.Part[64 + t] + S.Part[128 + t] + S.Part[192 + t];
        S.BU[t] = S.Part[256 + t] + S.Part[320 + t] + S.Part[384 + t] + S.Part[448 + t];
    }
    __syncthreads();

    // AP GEMM: 4(o) x 4(l) tile
    int o0 = (t >> 4) * 4, l0 = (t & 15) * 4;
    float acc[4][4];
#pragma unroll
    for (int i = 0; i < 4; i++) {
        float bi = S.BA[o0 + i];
#pragma unroll
        for (int j = 0; j < 4; j++) acc[i][j] = bi;
    }
#pragma unroll
    for (int c = 0; c < 8; c++) {
        float4 p = ld4(&S.Pa[c * 64 + o0]);
        float4 h = ld4(&S.Hmk[c * 64 + l0]);
        acc[0][0] += p.x * h.x; acc[0][1] += p.x * h.y; acc[0][2] += p.x * h.z; acc[0][3] += p.x * h.w;
        acc[1][0] += p.y * h.x; acc[1][1] += p.y * h.y; acc[1][2] += p.y * h.z; acc[1][3] += p.y * h.w;
        acc[2][0] += p.z * h.x; acc[2][1] += p.z * h.y; acc[2][2] += p.z * h.z; acc[2][3] += p.z * h.w;
        acc[3][0] += p.w * h.x; acc[3][1] += p.w * h.y; acc[3][2] += p.w * h.z; acc[3][3] += p.w * h.w;
    }
#pragma unroll
    for (int c = 0; c < 64; c++) {
        float4 qv = ld4(&g_TQa[c * 64 + o0]);
        float4 av = ld4(&S.AP[c * 64 + l0]);
        acc[0][0] += qv.x * av.x; acc[0][1] += qv.x * av.y; acc[0][2] += qv.x * av.z; acc[0][3] += qv.x * av.w;
        acc[1][0] += qv.y * av.x; acc[1][1] += qv.y * av.y; acc[1][2] += qv.y * av.z; acc[1][3] += qv.y * av.w;
        acc[2][0] += qv.z * av.x; acc[2][1] += qv.z * av.y; acc[2][2] += qv.z * av.z; acc[2][3] += qv.z * av.w;
        acc[3][0] += qv.w * av.x; acc[3][1] += qv.w * av.y; acc[3][2] += qv.w * av.z; acc[3][3] += qv.w * av.w;
    }

    // UE GEMM: 2(o) x 4(k) tile
    int ou = (t >> 3) * 2, kq = (t & 7) * 4;
    float au[2][4];
#pragma unroll
    for (int i = 0; i < 2; i++) {
        float bi = S.BU[ou + i];
#pragma unroll
        for (int j = 0; j < 4; j++) au[i][j] = bi;
    }
#pragma unroll
    for (int c = 0; c < 8; c++) {
        float2 p = ld2(&S.Pu[c * 64 + ou]);
        float4 h = ld4(&S.Hml[c * 32 + kq]);
        au[0][0] += p.x * h.x; au[0][1] += p.x * h.y; au[0][2] += p.x * h.z; au[0][3] += p.x * h.w;
        au[1][0] += p.y * h.x; au[1][1] += p.y * h.y; au[1][2] += p.y * h.z; au[1][3] += p.y * h.w;
    }
#pragma unroll
    for (int c = 0; c < 64; c++) {
        float2 qv = ld2(&g_TQu[c * 64 + ou]);
        float4 uv = ld4(&S.UE[c * 32 + kq]);
        au[0][0] += qv.x * uv.x; au[0][1] += qv.x * uv.y; au[0][2] += qv.x * uv.z; au[0][3] += qv.x * uv.w;
        au[1][0] += qv.y * uv.x; au[1][1] += qv.y * uv.y; au[1][2] += qv.y * uv.z; au[1][3] += qv.y * uv.w;
    }

    // epilogue fully in registers: relu, direct A1 store, shuffle-group stats
    float sA[4], sAS[4];
#pragma unroll
    for (int i = 0; i < 4; i++) {
        float r0 = fmaxf(acc[i][0], 0.f), r1 = fmaxf(acc[i][1], 0.f);
        float r2 = fmaxf(acc[i][2], 0.f), r3 = fmaxf(acc[i][3], 0.f);
        st4(&g_A1[(size_t)b * 4096 + (o0 + i) * 64 + l0], make_float4(r0, r1, r2, r3));
        sA[i] = r0 + r1 + r2 + r3;
        sAS[i] = r0 * r0 + r1 * r1 + r2 * r2 + r3 * r3;
    }
#pragma unroll
    for (int m = 1; m < 16; m <<= 1) {
#pragma unroll
        for (int i = 0; i < 4; i++) {
            sA[i] += __shfl_xor_sync(0xffffffffu, sA[i], m);
            sAS[i] += __shfl_xor_sync(0xffffffffu, sAS[i], m);
        }
    }
    if ((t & 15) == 0) {
#pragma unroll
        for (int i = 0; i < 4; i++) {
            atomicAdd(&g_stats[256 + o0 + i], sA[i]);
            atomicAdd(&g_stats[320 + o0 + i], sAS[i]);
        }
    }

    float sU[2], sUS[2];
#pragma unroll
    for (int i = 0; i < 2; i++) {
        float r0 = fmaxf(au[i][0], 0.f), r1 = fmaxf(au[i][1], 0.f);
        float r2 = fmaxf(au[i][2], 0.f), r3 = fmaxf(au[i][3], 0.f);
        sU[i] = r0 + r1 + r2 + r3;
        sUS[i] = r0 * r0 + r1 * r1 + r2 * r2 + r3 * r3;
    }
#pragma unroll
    for (int m = 1; m < 8; m <<= 1) {
#pragma unroll
        for (int i = 0; i < 2; i++) {
            sU[i] += __shfl_xor_sync(0xffffffffu, sU[i], m);
            sUS[i] += __shfl_xor_sync(0xffffffffu, sUS[i], m);
        }
    }
    if ((t & 7) == 0) {
#pragma unroll
        for (int i = 0; i < 2; i++) {
            atomicAdd(&g_stats[384 + ou + i], sU[i]);
            atomicAdd(&g_stats[448 + ou + i], sUS[i]);
            g_U1m[(size_t)b * 64 + ou + i] = sU[i] * (1.f / 32.f);
        }
    }
}

// ---------------- K3: output layer + per-k norm + fused Vhat*Phat stream ----------------
__global__ void __launch_bounds__(256) k3_fused(const float* __restrict__ gamma,
                                                const float* __restrict__ beta,
                                                const float* __restrict__ Vh,
                                                float* __restrict__ out) {
    __shared__ float sAP[4096];          // normalized layer1 AP [c][l]
    __shared__ float sPo[256];
    __shared__ float sHmk[512];
    __shared__ float sV[32 * 65];
    __shared__ float sPb[8 * 32];
    __shared__ float sMU[64], sB[32], sFac[32], sScA[64], sShA[64];
    int b = blockIdx.x, t = threadIdx.x;

    // prefetch raw A1 into registers
    float a_raw[16];
#pragma unroll
    for (int j = 0; j < 16; j++) a_raw[j] = g_A1[(size_t)b * 4096 + t + j * 256];

    if (t < 64) {
        float m = g_stats[256 + t] * (1.f / 65536.f);
        float v = g_stats[320 + t] * (1.f / 65536.f) - m * m;
        float sc = gamma[64 + t] * rsqrtf(v + EPS);
        sScA[t] = sc; sShA[t] = beta[64 + t] - m * sc;
        float mu = g_stats[384 + t] * (1.f / 32768.f);
        float vu = g_stats[448 + t] * (1.f / 32768.f) - mu * mu;
        float su = gamma[64 + t] * rsqrtf(vu + EPS);
        float sh = beta[64 + t] - mu * su;
        sMU[t] = g_U1m[(size_t)b * 64 + t] * su + sh;
    }
    sPo[t] = g_TPo[t];
    for (int i = t; i < 512; i += 256) sHmk[i] = g_Hmk[(size_t)b * 512 + i];
    __syncthreads();

#pragma unroll
    for (int j = 0; j < 16; j++) {
        int i = t + j * 256;
        int c = i >> 6;
        sAP[i] = a_raw[j] * sScA[c] + sShA[c];
    }
    {
        int k = t & 31, g = t >> 5;
        float s = 0.f;
#pragma unroll
        for (int j = 0; j < 8; j++) {
            int c = g * 8 + j;
            s += g_TQo2[c * 32 + k] * sMU[c];
        }
        sPb[g * 32 + k] = s;
    }
    __syncthreads();
    if (t < 32) {
        float s = 0.f;
#pragma unroll
        for (int g = 0; g < 8; g++) s += sPb[g * 32 + t];
        sB[t] = s;
    }
    __syncthreads();

    // GEMM 32(k) x 64(l) x 72: thread tile 4(k) x 2(l)
    int ko = (t >> 5) * 4, lo = (t & 31) * 2;
    float acc[4][2];
#pragma unroll
    for (int i = 0; i < 4; i++) { acc[i][0] = sB[ko + i]; acc[i][1] = sB[ko + i]; }
#pragma unroll
    for (int c = 0; c < 8; c++) {
        float4 p = ld4(&sPo[c * 32 + ko]);
        float h0 = sHmk[c * 64 + lo], h1 = sHmk[c * 64 + lo + 1];
        acc[0][0] += p.x * h0; acc[0][1] += p.x * h1;
        acc[1][0] += p.y * h0; acc[1][1] += p.y * h1;
        acc[2][0] += p.z * h0; acc[2][1] += p.z * h1;
        acc[3][0] += p.w * h0; acc[3][1] += p.w * h1;
    }
#pragma unroll
    for (int c = 0; c < 64; c++) {
        float4 qv = ld4(&g_TQo[c * 32 + ko]);
        float2 a = ld2(&sAP[c * 64 + lo]);
        acc[0][0] += qv.x * a.x; acc[0][1] += qv.x * a.y;
        acc[1][0] += qv.y * a.x; acc[1][1] += qv.y * a.y;
        acc[2][0] += qv.z * a.x; acc[2][1] += qv.z * a.y;
        acc[3][0] += qv.w * a.x; acc[3][1] += qv.w * a.y;
    }
#pragma unroll
    for (int i = 0; i < 4; i++) {
        sV[(ko + i) * 65 + lo] = acc[i][0];
        sV[(ko + i) * 65 + lo + 1] = acc[i][1];
    }
    __syncthreads();

    // per-k norm: 8 lanes per k, shuffle reduce
    {
        int k = t >> 3, j = t & 7;
        float ss = 0.f;
#pragma unroll
        for (int i = 0; i < 8; i++) {
            float x = sV[k * 65 + j * 8 + i];
            ss += x * x;
        }
        ss += __shfl_xor_sync(0xffffffffu, ss, 1);
        ss += __shfl_xor_sync(0xffffffffu, ss, 2);
        ss += __shfl_xor_sync(0xffffffffu, ss, 4);
        if (j == 0) sFac[k] = 8.f * rsqrtf(ss);       // sqrt(L)=8
    }
    __syncthreads();

    // fused stream: out[b,l,k,:] = Vhat[b,l,k,:] * Phat[b,l,k]
    const float4* v4 = reinterpret_cast<const float4*>(Vh) + (size_t)b * 2048;
    float4* o4 = reinterpret_cast<float4*>(out) + (size_t)b * 2048;
#pragma unroll
    for (int j = 0; j < 8; j++) {
        int i = t + j * 256;
        int l = i >> 5, k = i & 31;
        float pf = sV[k * 65 + l] * sFac[k];
        float4 v = v4[i];
        v.x *= pf; v.y *= pf; v.z *= pf; v.w *= pf;
        o4[i] = v;
    }
}

// ---------------- host ----------------
extern "C" void kernel_launch(void* const* d_in, const int* in_sizes, int n_in,
                              void* d_out, int out_size) {
    (void)in_sizes; (void)n_in; (void)out_size;
    const float* Hr = (const float*)d_in[0];
    const float* Hi = (const float*)d_in[1];
    const float* Vh = (const float*)d_in[2];
    const float* Qh = (const float*)d_in[3];
    const float* Ph = (const float*)d_in[4];
    const float* Qo = (const float*)d_in[5];
    const float* Po = (const float*)d_in[6];
    const float* gamma = (const float*)d_in[7];
    const float* beta = (const float*)d_in[8];

    static int attr_done = 0;
    if (!attr_done) {
        cudaFuncSetAttribute(k1_l0, cudaFuncAttributeMaxDynamicSharedMemorySize, (int)sizeof(SK1));
        cudaFuncSetAttribute(k2_full, cudaFuncAttributeMaxDynamicSharedMemorySize, (int)sizeof(SK2));
        attr_done = 1;
    }

    k0_prep<<<16, 256>>>(Qh, Ph, Qo, Po);
    k1_l0<<<1024, 256, sizeof(SK1)>>>(Hr, Hi, Ph);
    k2_full<<<1024, 256, sizeof(SK2)>>>(Ph, gamma, beta);
    k3_fused<<<1024, 256>>>(gamma, beta, Vh, (float*)d_out);
}